// round 7
// baseline (speedup 1.0000x reference)
#include <cuda_runtime.h>
#include <cstdint>

// FOFE encoding:
//   out[b,s,v] = sum_k alpha^(W-1-k) * [sents[b,s,k] == v],  V=512, W=20
// R2 structure (warp per row, smem accumulate) with WRITE-THROUGH output
// stores (__stwt): no L2 write-allocate -> no dirty-eviction second pass
// through LTS in the steady-state graph-replay loop.

#define FOFE_V 512
#define FOFE_W 20
#define WARPS_PER_BLOCK 8

__global__ void __launch_bounds__(WARPS_PER_BLOCK * 32)
fofe_kernel(const int* __restrict__ sents,
            const int* __restrict__ lengths,
            const float* __restrict__ forgetting,
            float* __restrict__ out,
            int n_rows, int tail_n) {
    __shared__ float sh[WARPS_PER_BLOCK][FOFE_V];

    const int warp = threadIdx.x >> 5;
    const int lane = threadIdx.x & 31;
    const int row  = blockIdx.x * WARPS_PER_BLOCK + warp;

    // fused lengths tail (block 0, <=256 values)
    if (blockIdx.x == 0 && (int)threadIdx.x < tail_n) {
        out[(size_t)n_rows * FOFE_V + threadIdx.x] = (float)lengths[threadIdx.x];
    }
    if (row >= n_rows) return;

    float* s = sh[warp];
    float4* s4 = reinterpret_cast<float4*>(s);

    // zero 512 floats via 4 x STS.128 per lane
    const float4 z4 = make_float4(0.f, 0.f, 0.f, 0.f);
    #pragma unroll
    for (int i = 0; i < 4; i++) s4[lane + i * 32] = z4;
    __syncwarp();

    // lanes 0..19: scatter-add decay weight into shared
    if (lane < FOFE_W) {
        const float alpha = __ldg(forgetting);
        const int c = sents[(size_t)row * FOFE_W + lane];
        float w = 1.0f;
        const int e = FOFE_W - 1 - lane;
        #pragma unroll
        for (int j = 0; j < FOFE_W - 1; j++) {
            if (j < e) w *= alpha;
        }
        atomicAdd(&s[c], w);
    }
    __syncwarp();

    // stream out 512 floats: 4 x STG.128 write-through per lane
    float4* orow = reinterpret_cast<float4*>(out + (size_t)row * FOFE_V);
    #pragma unroll
    for (int i = 0; i < 4; i++) {
        const int idx = lane + i * 32;
        __stwt(orow + idx, s4[idx]);
    }
}

extern "C" void kernel_launch(void* const* d_in, const int* in_sizes, int n_in,
                              void* d_out, int out_size) {
    const int*   sents      = (const int*)d_in[0];
    const int*   lengths    = (const int*)d_in[1];
    const float* forgetting = (const float*)d_in[2];
    float*       out        = (float*)d_out;

    const int n_rows = in_sizes[0] / FOFE_W;      // B*S
    const int B      = in_sizes[1];

    const long long main_elems = (long long)n_rows * FOFE_V;
    int tail_n = 0;
    if ((long long)out_size > main_elems) {
        long long t = (long long)out_size - main_elems;
        tail_n = (int)(t < B ? t : B);
        if (tail_n > 256) tail_n = 256;
    }

    const int threads = WARPS_PER_BLOCK * 32;
    const int blocks  = (n_rows + WARPS_PER_BLOCK - 1) / WARPS_PER_BLOCK;
    fofe_kernel<<<blocks, threads>>>(sents, lengths, forgetting, out,
                                     n_rows, tail_n);
}